// round 2
// baseline (speedup 1.0000x reference)
#include <cuda_runtime.h>
#include <cuda_bf16.h>

// Fixed shapes per reference setup_inputs
#define BB 8
#define CC 3
#define HH 224
#define WW 224
#define NPIX (HH * WW)          // 50176
#define NSEG 196
#define EE 768
#define NROWS (BB * NSEG)       // 1568
#define ACC_STRIDE 8            // [sum_r, sum_g, sum_b, sum_x, sum_y, cnt, pad, pad]

#define NBLOCKS 392             // = (BB*NPIX/4) / 256 exactly; also NROWS/4 rows each
#define NTHREADS 256

// Scratch accumulator: zero at module load; each launch leaves it zeroed.
__device__ float g_acc[NROWS * ACC_STRIDE];
// Grid-barrier counters: zero at module load; each launch leaves them zeroed.
__device__ unsigned int g_bar_arrive;
__device__ unsigned int g_bar_exit;

// ---------------------------------------------------------------------------
// Vector global reductions (sm_90+): 2 RED ops per pixel instead of 6
// ---------------------------------------------------------------------------
__device__ __forceinline__ void red_add_v4(float* addr, float a, float b,
                                           float c, float d) {
    asm volatile("red.global.add.v4.f32 [%0], {%1, %2, %3, %4};"
                 :: "l"(addr), "f"(a), "f"(b), "f"(c), "f"(d) : "memory");
}
__device__ __forceinline__ void red_add_v2(float* addr, float a, float b) {
    asm volatile("red.global.add.v2.f32 [%0], {%1, %2};"
                 :: "l"(addr), "f"(a), "f"(b) : "memory");
}
// L2-only load (REDG results live in L2, never in L1)
__device__ __forceinline__ float ld_cg(const float* p) {
    float v;
    asm volatile("ld.global.cg.f32 %0, [%1];" : "=f"(v) : "l"(p));
    return v;
}

// ---------------------------------------------------------------------------
// Single fused kernel:
//   Phase A: scatter per-(batch,segment) feature sums via vector REDG
//   Grid barrier (spin on atomic counter; 392 blocks are fully co-resident)
//   Phase B: project 4 segment rows per block, then reset those acc rows to 0
//   Exit: last block resets barrier counters for the next graph replay
// ---------------------------------------------------------------------------
__global__ void __launch_bounds__(NTHREADS, 8)
fused_kernel(const float* __restrict__ img,
             const int* __restrict__ seg,
             const float* __restrict__ Wm,
             const float* __restrict__ bias,
             float* __restrict__ out) {
    // ---------------- Phase A: scatter ----------------
    int t = blockIdx.x * NTHREADS + threadIdx.x;     // exactly one 4-pixel group
    {
        int b  = t / (NPIX / 4);
        int n4 = t - b * (NPIX / 4);
        int n  = n4 * 4;                             // pixel linear index
        int h  = n / WW;
        int w  = n - h * WW;

        const float4 r4 = *reinterpret_cast<const float4*>(img + ((long)(b * CC + 0) * NPIX + n));
        const float4 g4 = *reinterpret_cast<const float4*>(img + ((long)(b * CC + 1) * NPIX + n));
        const float4 b4 = *reinterpret_cast<const float4*>(img + ((long)(b * CC + 2) * NPIX + n));
        const int4   s4 = *reinterpret_cast<const int4*>(seg + (long)b * NPIX + n);

        const float inv = 1.0f / 223.0f;
        float y = (float)h * inv;

        float rr[4] = {r4.x, r4.y, r4.z, r4.w};
        float gg[4] = {g4.x, g4.y, g4.z, g4.w};
        float bb[4] = {b4.x, b4.y, b4.z, b4.w};
        int   ss[4] = {s4.x, s4.y, s4.z, s4.w};

#pragma unroll
        for (int i = 0; i < 4; i++) {
            float x = (float)(w + i) * inv;
            float* base = g_acc + (long)(b * NSEG + ss[i]) * ACC_STRIDE;
            red_add_v4(base, rr[i], gg[i], bb[i], x);
            red_add_v2(base + 4, y, 1.0f);
        }
    }

    // ---------------- Grid barrier ----------------
    __syncthreads();
    __threadfence();                                 // commit this block's REDs
    if (threadIdx.x == 0) {
        atomicAdd(&g_bar_arrive, 1u);
        while (atomicAdd(&g_bar_arrive, 0u) < (unsigned)gridDim.x) { }
    }
    __syncthreads();

    // ---------------- Phase B: projection (4 rows per block) ----------------
    {
        int row0 = blockIdx.x * 4;
#pragma unroll
        for (int r = 0; r < 4; r++) {
            int s = row0 + r;
            const float* a = g_acc + (long)s * ACC_STRIDE;
            float cnt = ld_cg(a + 5);
            bool  empty = !(cnt > 0.0f);
            float invc = empty ? 0.0f : (1.0f / cnt);
            float m0 = ld_cg(a + 0) * invc;
            float m1 = ld_cg(a + 1) * invc;
            float m2 = ld_cg(a + 2) * invc;
            float m3 = ld_cg(a + 3) * invc;
            float m4 = ld_cg(a + 4) * invc;

            float* orow = out + (long)s * EE;
#pragma unroll
            for (int k = 0; k < 3; k++) {
                int e = threadIdx.x + k * NTHREADS;
                float v = m0 * Wm[e]
                        + m1 * Wm[EE + e]
                        + m2 * Wm[2 * EE + e]
                        + m3 * Wm[3 * EE + e]
                        + m4 * Wm[4 * EE + e]
                        + bias[e];
                orow[e] = empty ? 0.0f : v;
            }
        }
        // Reset this block's acc rows to zero for the next replay.
        // 4 rows * 8 floats = 32 floats = 8 float4 stores.
        __syncthreads();   // ensure all reads of these rows are done
        if (threadIdx.x < 8) {
            reinterpret_cast<float4*>(g_acc + (long)row0 * ACC_STRIDE)[threadIdx.x] =
                make_float4(0.f, 0.f, 0.f, 0.f);
        }
    }

    // ---------------- Exit: last block resets barrier counters ----------------
    __syncthreads();
    __threadfence();
    if (threadIdx.x == 0) {
        unsigned old = atomicAdd(&g_bar_exit, 1u);
        if (old == (unsigned)gridDim.x - 1u) {
            // Everyone has passed the arrive-barrier and finished; nobody reads
            // these again in this launch.
            g_bar_arrive = 0u;
            g_bar_exit = 0u;
            __threadfence();
        }
    }
}

// ---------------------------------------------------------------------------
extern "C" void kernel_launch(void* const* d_in, const int* in_sizes, int n_in,
                              void* d_out, int out_size) {
    const float* img  = (const float*)d_in[0];   // [8,3,224,224]
    const int*   seg  = (const int*)d_in[1];     // [8,224,224]
    const float* Wm   = (const float*)d_in[2];   // [5,768]
    const float* bias = (const float*)d_in[3];   // [768]
    float* out = (float*)d_out;                  // [8,196,768]

    (void)in_sizes; (void)n_in; (void)out_size;

    fused_kernel<<<NBLOCKS, NTHREADS>>>(img, seg, Wm, bias, out);
}

// round 3
// speedup vs baseline: 1.0015x; 1.0015x over previous
#include <cuda_runtime.h>
#include <cuda_bf16.h>

// Fixed shapes per reference setup_inputs
#define BB 8
#define CC 3
#define HH 224
#define WW 224
#define NPIX (HH * WW)          // 50176
#define NSEG 196
#define EE 768
#define NROWS (BB * NSEG)       // 1568
#define ACC_STRIDE 8            // [sum_r, sum_g, sum_b, sum_x, sum_y, cnt, pad, pad]
#define NREP 4                  // accumulator replicas (chain-length reduction)

#define NBLOCKS 392             // = (BB*NPIX/4) / 256 exactly; also NROWS/4 rows each
#define NTHREADS 256

// Scratch accumulators: zero at module load; each launch leaves them zeroed.
__device__ float g_acc[NREP * NROWS * ACC_STRIDE];   // 200704 B
// Grid-barrier counters: zero at module load; each launch leaves them zeroed.
__device__ unsigned int g_bar_arrive;
__device__ unsigned int g_bar_exit;

// ---------------------------------------------------------------------------
__device__ __forceinline__ void red_add_v4(float* addr, float a, float b,
                                           float c, float d) {
    asm volatile("red.global.add.v4.f32 [%0], {%1, %2, %3, %4};"
                 :: "l"(addr), "f"(a), "f"(b), "f"(c), "f"(d) : "memory");
}
__device__ __forceinline__ void red_add_v2(float* addr, float a, float b) {
    asm volatile("red.global.add.v2.f32 [%0], {%1, %2};"
                 :: "l"(addr), "f"(a), "f"(b) : "memory");
}
__device__ __forceinline__ float ld_cg(const float* p) {
    float v;
    asm volatile("ld.global.cg.f32 %0, [%1];" : "=f"(v) : "l"(p));
    return v;
}
__device__ __forceinline__ unsigned int ld_acquire_gpu(const unsigned int* p) {
    unsigned int v;
    asm volatile("ld.global.acquire.gpu.u32 %0, [%1];" : "=r"(v) : "l"(p));
    return v;
}

// ---------------------------------------------------------------------------
// Single fused kernel:
//   Phase A: scatter per-(batch,segment) feature sums via vector REDG into
//            one of NREP replica accumulators (chosen by blockIdx & 3)
//   Grid barrier: one atomicAdd arrive, then NON-ATOMIC acquire-load polling
//   Phase B: project 4 segment rows per block (summing replicas), reset acc
//   Exit: last block resets barrier counters for the next graph replay
// ---------------------------------------------------------------------------
__global__ void __launch_bounds__(NTHREADS, 8)
fused_kernel(const float* __restrict__ img,
             const int* __restrict__ seg,
             const float* __restrict__ Wm,
             const float* __restrict__ bias,
             float* __restrict__ out) {
    // ---------------- Phase A: scatter ----------------
    {
        int t  = blockIdx.x * NTHREADS + threadIdx.x;   // one 4-pixel group
        int b  = t / (NPIX / 4);
        int n4 = t - b * (NPIX / 4);
        int n  = n4 * 4;                                // pixel linear index
        int h  = n / WW;
        int w  = n - h * WW;

        const float4 r4 = *reinterpret_cast<const float4*>(img + ((long)(b * CC + 0) * NPIX + n));
        const float4 g4 = *reinterpret_cast<const float4*>(img + ((long)(b * CC + 1) * NPIX + n));
        const float4 b4 = *reinterpret_cast<const float4*>(img + ((long)(b * CC + 2) * NPIX + n));
        const int4   s4 = *reinterpret_cast<const int4*>(seg + (long)b * NPIX + n);

        const float inv = 1.0f / 223.0f;
        float y = (float)h * inv;

        float rr[4] = {r4.x, r4.y, r4.z, r4.w};
        float gg[4] = {g4.x, g4.y, g4.z, g4.w};
        float bb[4] = {b4.x, b4.y, b4.z, b4.w};
        int   ss[4] = {s4.x, s4.y, s4.z, s4.w};

        float* rep = g_acc + (long)(blockIdx.x & (NREP - 1)) * (NROWS * ACC_STRIDE);

#pragma unroll
        for (int i = 0; i < 4; i++) {
            float x = (float)(w + i) * inv;
            float* base = rep + (long)(b * NSEG + ss[i]) * ACC_STRIDE;
            red_add_v4(base, rr[i], gg[i], bb[i], x);
            red_add_v2(base + 4, y, 1.0f);
        }
    }

    // ---------------- Grid barrier ----------------
    __syncthreads();
    __threadfence();                                 // commit this block's REDs
    if (threadIdx.x == 0) {
        atomicAdd(&g_bar_arrive, 1u);                // single atomic per block
        while (ld_acquire_gpu(&g_bar_arrive) < (unsigned)gridDim.x) {
            __nanosleep(64);                         // non-atomic polling
        }
    }
    __syncthreads();

    // ---------------- Phase B: projection (4 rows per block) ----------------
    {
        int row0 = blockIdx.x * 4;
#pragma unroll
        for (int r = 0; r < 4; r++) {
            int s = row0 + r;
            float a0 = 0.f, a1 = 0.f, a2 = 0.f, a3 = 0.f, a4 = 0.f, cnt = 0.f;
#pragma unroll
            for (int rep = 0; rep < NREP; rep++) {
                const float* a = g_acc + (long)rep * (NROWS * ACC_STRIDE)
                                       + (long)s * ACC_STRIDE;
                a0  += ld_cg(a + 0);
                a1  += ld_cg(a + 1);
                a2  += ld_cg(a + 2);
                a3  += ld_cg(a + 3);
                a4  += ld_cg(a + 4);
                cnt += ld_cg(a + 5);
            }
            bool  empty = !(cnt > 0.0f);
            float invc = empty ? 0.0f : (1.0f / cnt);
            float m0 = a0 * invc;
            float m1 = a1 * invc;
            float m2 = a2 * invc;
            float m3 = a3 * invc;
            float m4 = a4 * invc;

            float* orow = out + (long)s * EE;
#pragma unroll
            for (int k = 0; k < 3; k++) {
                int e = threadIdx.x + k * NTHREADS;
                float v = m0 * Wm[e]
                        + m1 * Wm[EE + e]
                        + m2 * Wm[2 * EE + e]
                        + m3 * Wm[3 * EE + e]
                        + m4 * Wm[4 * EE + e]
                        + bias[e];
                orow[e] = empty ? 0.0f : v;
            }
        }
        // Reset this block's acc rows (all replicas) for the next replay:
        // 4 rows * 8 floats * NREP = 128 floats = 32 float4 stores.
        __syncthreads();   // ensure all reads of these rows are done
        if (threadIdx.x < 8 * NREP) {
            int rep = threadIdx.x / 8;
            int idx = threadIdx.x % 8;
            reinterpret_cast<float4*>(g_acc + (long)rep * (NROWS * ACC_STRIDE)
                                            + (long)row0 * ACC_STRIDE)[idx] =
                make_float4(0.f, 0.f, 0.f, 0.f);
        }
    }

    // ---------------- Exit: last block resets barrier counters ----------------
    __syncthreads();
    __threadfence();
    if (threadIdx.x == 0) {
        unsigned old = atomicAdd(&g_bar_exit, 1u);
        if (old == (unsigned)gridDim.x - 1u) {
            g_bar_arrive = 0u;
            g_bar_exit = 0u;
            __threadfence();
        }
    }
}

// ---------------------------------------------------------------------------
extern "C" void kernel_launch(void* const* d_in, const int* in_sizes, int n_in,
                              void* d_out, int out_size) {
    const float* img  = (const float*)d_in[0];   // [8,3,224,224]
    const int*   seg  = (const int*)d_in[1];     // [8,224,224]
    const float* Wm   = (const float*)d_in[2];   // [5,768]
    const float* bias = (const float*)d_in[3];   // [768]
    float* out = (float*)d_out;                  // [8,196,768]

    (void)in_sizes; (void)n_in; (void)out_size;

    fused_kernel<<<NBLOCKS, NTHREADS>>>(img, seg, Wm, bias, out);
}

// round 4
// speedup vs baseline: 1.0391x; 1.0376x over previous
#include <cuda_runtime.h>
#include <cuda_bf16.h>

// Fixed shapes per reference setup_inputs
#define BB 8
#define CC 3
#define HH 224
#define WW 224
#define NPIX (HH * WW)          // 50176
#define NSEG 196
#define EE 768
#define NROWS (BB * NSEG)       // 1568
#define ACC_STRIDE 64           // 256 B per row: one LTS hash block per (rep,row)
#define NREP 4                  // accumulator replicas

#define NBLOCKS 392             // = (BB*NPIX/4) / 256 exactly; also NROWS/4 rows each
#define NTHREADS 256

// Scratch accumulators: 4 * 1568 * 256 B = 1.6 MB. Zero at module load; each
// launch leaves them zeroed. Layout per row: [r, g, b, x, y, cnt, pad...].
__device__ float g_acc[(long)NREP * NROWS * ACC_STRIDE];
// Grid-barrier counters: zero at module load; each launch leaves them zeroed.
__device__ unsigned int g_bar_arrive;
__device__ unsigned int g_bar_exit;

// ---------------------------------------------------------------------------
__device__ __forceinline__ void red_add_v4(float* addr, float a, float b,
                                           float c, float d) {
    asm volatile("red.global.add.v4.f32 [%0], {%1, %2, %3, %4};"
                 :: "l"(addr), "f"(a), "f"(b), "f"(c), "f"(d) : "memory");
}
__device__ __forceinline__ void red_add_v2(float* addr, float a, float b) {
    asm volatile("red.global.add.v2.f32 [%0], {%1, %2};"
                 :: "l"(addr), "f"(a), "f"(b) : "memory");
}
__device__ __forceinline__ float ld_cg(const float* p) {
    float v;
    asm volatile("ld.global.cg.f32 %0, [%1];" : "=f"(v) : "l"(p));
    return v;
}
__device__ __forceinline__ unsigned int ld_acquire_gpu(const unsigned int* p) {
    unsigned int v;
    asm volatile("ld.global.acquire.gpu.u32 %0, [%1];" : "=r"(v) : "l"(p));
    return v;
}

// ---------------------------------------------------------------------------
__global__ void __launch_bounds__(NTHREADS, 8)
fused_kernel(const float* __restrict__ img,
             const int* __restrict__ seg,
             const float* __restrict__ Wm,
             const float* __restrict__ bias,
             float* __restrict__ out) {
    // ---------------- Phase A: scatter ----------------
    {
        int t  = blockIdx.x * NTHREADS + threadIdx.x;   // one 4-pixel group
        int b  = t / (NPIX / 4);
        int n4 = t - b * (NPIX / 4);
        int n  = n4 * 4;                                // pixel linear index
        int h  = n / WW;
        int w  = n - h * WW;

        const float4 r4 = *reinterpret_cast<const float4*>(img + ((long)(b * CC + 0) * NPIX + n));
        const float4 g4 = *reinterpret_cast<const float4*>(img + ((long)(b * CC + 1) * NPIX + n));
        const float4 b4 = *reinterpret_cast<const float4*>(img + ((long)(b * CC + 2) * NPIX + n));
        const int4   s4 = *reinterpret_cast<const int4*>(seg + (long)b * NPIX + n);

        const float inv = 1.0f / 223.0f;
        float y = (float)h * inv;

        float rr[4] = {r4.x, r4.y, r4.z, r4.w};
        float gg[4] = {g4.x, g4.y, g4.z, g4.w};
        float bb[4] = {b4.x, b4.y, b4.z, b4.w};
        int   ss[4] = {s4.x, s4.y, s4.z, s4.w};

        float* rep = g_acc + (long)(blockIdx.x & (NREP - 1)) * ((long)NROWS * ACC_STRIDE);

#pragma unroll
        for (int i = 0; i < 4; i++) {
            float x = (float)(w + i) * inv;
            float* base = rep + (long)(b * NSEG + ss[i]) * ACC_STRIDE;
            red_add_v4(base, rr[i], gg[i], bb[i], x);
            red_add_v2(base + 4, y, 1.0f);
        }
    }

    // ---------------- Grid barrier ----------------
    __syncthreads();
    __threadfence();                                 // commit this block's REDs
    if (threadIdx.x == 0) {
        atomicAdd(&g_bar_arrive, 1u);                // single atomic per block
        while (ld_acquire_gpu(&g_bar_arrive) < (unsigned)gridDim.x) {
            __nanosleep(64);                         // non-atomic polling
        }
    }
    __syncthreads();

    // ---------------- Phase B: projection (4 rows per block) ----------------
    {
        int row0 = blockIdx.x * 4;
#pragma unroll
        for (int r = 0; r < 4; r++) {
            int s = row0 + r;
            float a0 = 0.f, a1 = 0.f, a2 = 0.f, a3 = 0.f, a4 = 0.f, cnt = 0.f;
#pragma unroll
            for (int rep = 0; rep < NREP; rep++) {
                const float* a = g_acc + (long)rep * ((long)NROWS * ACC_STRIDE)
                                       + (long)s * ACC_STRIDE;
                a0  += ld_cg(a + 0);
                a1  += ld_cg(a + 1);
                a2  += ld_cg(a + 2);
                a3  += ld_cg(a + 3);
                a4  += ld_cg(a + 4);
                cnt += ld_cg(a + 5);
            }
            bool  empty = !(cnt > 0.0f);
            float invc = empty ? 0.0f : (1.0f / cnt);
            float m0 = a0 * invc;
            float m1 = a1 * invc;
            float m2 = a2 * invc;
            float m3 = a3 * invc;
            float m4 = a4 * invc;

            float* orow = out + (long)s * EE;
#pragma unroll
            for (int k = 0; k < 3; k++) {
                int e = threadIdx.x + k * NTHREADS;
                float v = m0 * Wm[e]
                        + m1 * Wm[EE + e]
                        + m2 * Wm[2 * EE + e]
                        + m3 * Wm[3 * EE + e]
                        + m4 * Wm[4 * EE + e]
                        + bias[e];
                orow[e] = empty ? 0.0f : v;
            }
        }
        // Reset this block's acc rows (all replicas) for the next replay.
        // Only the first 8 floats of each row are ever nonzero:
        // 4 rows * NREP reps * 2 float4 = 32 float4 stores.
        __syncthreads();   // ensure all reads of these rows are done
        if (threadIdx.x < 8 * NREP) {
            int rep = threadIdx.x / 8;        // 0..3
            int q   = threadIdx.x % 8;        // 0..7 -> row = q/2, half = q%2
            int row = row0 + (q >> 1);
            int half = q & 1;
            reinterpret_cast<float4*>(g_acc + (long)rep * ((long)NROWS * ACC_STRIDE)
                                            + (long)row * ACC_STRIDE)[half] =
                make_float4(0.f, 0.f, 0.f, 0.f);
        }
    }

    // ---------------- Exit: last block resets barrier counters ----------------
    __syncthreads();
    __threadfence();
    if (threadIdx.x == 0) {
        unsigned old = atomicAdd(&g_bar_exit, 1u);
        if (old == (unsigned)gridDim.x - 1u) {
            g_bar_arrive = 0u;
            g_bar_exit = 0u;
            __threadfence();
        }
    }
}

// ---------------------------------------------------------------------------
extern "C" void kernel_launch(void* const* d_in, const int* in_sizes, int n_in,
                              void* d_out, int out_size) {
    const float* img  = (const float*)d_in[0];   // [8,3,224,224]
    const int*   seg  = (const int*)d_in[1];     // [8,224,224]
    const float* Wm   = (const float*)d_in[2];   // [5,768]
    const float* bias = (const float*)d_in[3];   // [768]
    float* out = (float*)d_out;                  // [8,196,768]

    (void)in_sizes; (void)n_in; (void)out_size;

    fused_kernel<<<NBLOCKS, NTHREADS>>>(img, seg, Wm, bias, out);
}

// round 5
// speedup vs baseline: 1.1085x; 1.0668x over previous
#include <cuda_runtime.h>
#include <cuda_bf16.h>

// Fixed shapes per reference setup_inputs
#define BB 8
#define CC 3
#define HH 224
#define WW 224
#define NPIX (HH * WW)          // 50176
#define NSEG 196
#define EE 768
#define NROWS (BB * NSEG)       // 1568
#define ACC_STRIDE 64           // 256 B per row: one LTS hash block per (rep,row)
#define NREP 4                  // accumulator replicas

#define NBLOCKS 392             // = (BB*NPIX/4) / 256 exactly; also NROWS/4 rows each
#define NTHREADS 256

// Scratch accumulators: 4 * 1568 * 256 B = 1.6 MB. Zero at module load; the
// project kernel re-zeroes every row it consumes, so each launch leaves the
// array zeroed for the next graph replay.
__device__ float g_acc[(long)NREP * NROWS * ACC_STRIDE];

// ---------------------------------------------------------------------------
__device__ __forceinline__ void red_add_v4(float* addr, float a, float b,
                                           float c, float d) {
    asm volatile("red.global.add.v4.f32 [%0], {%1, %2, %3, %4};"
                 :: "l"(addr), "f"(a), "f"(b), "f"(c), "f"(d) : "memory");
}
__device__ __forceinline__ void red_add_v2(float* addr, float a, float b) {
    asm volatile("red.global.add.v2.f32 [%0], {%1, %2};"
                 :: "l"(addr), "f"(a), "f"(b) : "memory");
}
__device__ __forceinline__ float ld_cg(const float* p) {
    float v;
    asm volatile("ld.global.cg.f32 %0, [%1];" : "=f"(v) : "l"(p));
    return v;
}

// ---------------------------------------------------------------------------
// Kernel A: scatter per-(batch,segment) feature sums via vector REDG into
// one of NREP replica accumulators (chosen by blockIdx & 3).
// ---------------------------------------------------------------------------
__global__ void __launch_bounds__(NTHREADS, 8)
scatter_kernel(const float* __restrict__ img,
               const int* __restrict__ seg) {
    int t  = blockIdx.x * NTHREADS + threadIdx.x;   // one 4-pixel group
    int b  = t / (NPIX / 4);
    int n4 = t - b * (NPIX / 4);
    int n  = n4 * 4;                                // pixel linear index
    int h  = n / WW;
    int w  = n - h * WW;

    const float4 r4 = *reinterpret_cast<const float4*>(img + ((long)(b * CC + 0) * NPIX + n));
    const float4 g4 = *reinterpret_cast<const float4*>(img + ((long)(b * CC + 1) * NPIX + n));
    const float4 b4 = *reinterpret_cast<const float4*>(img + ((long)(b * CC + 2) * NPIX + n));
    const int4   s4 = *reinterpret_cast<const int4*>(seg + (long)b * NPIX + n);

    const float inv = 1.0f / 223.0f;
    float y = (float)h * inv;

    float rr[4] = {r4.x, r4.y, r4.z, r4.w};
    float gg[4] = {g4.x, g4.y, g4.z, g4.w};
    float bb[4] = {b4.x, b4.y, b4.z, b4.w};
    int   ss[4] = {s4.x, s4.y, s4.z, s4.w};

    float* rep = g_acc + (long)(blockIdx.x & (NREP - 1)) * ((long)NROWS * ACC_STRIDE);

#pragma unroll
    for (int i = 0; i < 4; i++) {
        float x = (float)(w + i) * inv;
        float* base = rep + (long)(b * NSEG + ss[i]) * ACC_STRIDE;
        red_add_v4(base, rr[i], gg[i], bb[i], x);
        red_add_v2(base + 4, y, 1.0f);
    }
}

// ---------------------------------------------------------------------------
// Kernel B: project 4 segment rows per block (summing replicas), then reset
// those acc rows to zero for the next graph replay.
// ---------------------------------------------------------------------------
__global__ void __launch_bounds__(NTHREADS, 8)
project_kernel(const float* __restrict__ Wm,
               const float* __restrict__ bias,
               float* __restrict__ out) {
    int row0 = blockIdx.x * 4;
#pragma unroll
    for (int r = 0; r < 4; r++) {
        int s = row0 + r;
        float a0 = 0.f, a1 = 0.f, a2 = 0.f, a3 = 0.f, a4 = 0.f, cnt = 0.f;
#pragma unroll
        for (int rep = 0; rep < NREP; rep++) {
            const float* a = g_acc + (long)rep * ((long)NROWS * ACC_STRIDE)
                                   + (long)s * ACC_STRIDE;
            a0  += ld_cg(a + 0);
            a1  += ld_cg(a + 1);
            a2  += ld_cg(a + 2);
            a3  += ld_cg(a + 3);
            a4  += ld_cg(a + 4);
            cnt += ld_cg(a + 5);
        }
        bool  empty = !(cnt > 0.0f);
        float invc = empty ? 0.0f : (1.0f / cnt);
        float m0 = a0 * invc;
        float m1 = a1 * invc;
        float m2 = a2 * invc;
        float m3 = a3 * invc;
        float m4 = a4 * invc;

        float* orow = out + (long)s * EE;
#pragma unroll
        for (int k = 0; k < 3; k++) {
            int e = threadIdx.x + k * NTHREADS;
            float v = m0 * Wm[e]
                    + m1 * Wm[EE + e]
                    + m2 * Wm[2 * EE + e]
                    + m3 * Wm[3 * EE + e]
                    + m4 * Wm[4 * EE + e]
                    + bias[e];
            orow[e] = empty ? 0.0f : v;
        }
    }
    // Reset this block's acc rows (all replicas): only the first 8 floats of
    // each row are ever nonzero -> 4 rows * NREP * 2 float4 = 32 stores.
    __syncthreads();   // all reads of these rows are done
    if (threadIdx.x < 8 * NREP) {
        int rep  = threadIdx.x / 8;        // 0..3
        int q    = threadIdx.x % 8;        // row = q/2, half = q%2
        int row  = row0 + (q >> 1);
        int half = q & 1;
        reinterpret_cast<float4*>(g_acc + (long)rep * ((long)NROWS * ACC_STRIDE)
                                        + (long)row * ACC_STRIDE)[half] =
            make_float4(0.f, 0.f, 0.f, 0.f);
    }
}

// ---------------------------------------------------------------------------
extern "C" void kernel_launch(void* const* d_in, const int* in_sizes, int n_in,
                              void* d_out, int out_size) {
    const float* img  = (const float*)d_in[0];   // [8,3,224,224]
    const int*   seg  = (const int*)d_in[1];     // [8,224,224]
    const float* Wm   = (const float*)d_in[2];   // [5,768]
    const float* bias = (const float*)d_in[3];   // [768]
    float* out = (float*)d_out;                  // [8,196,768]

    (void)in_sizes; (void)n_in; (void)out_size;

    scatter_kernel<<<NBLOCKS, NTHREADS>>>(img, seg);
    project_kernel<<<NBLOCKS, NTHREADS>>>(Wm, bias, out);
}

// round 6
// speedup vs baseline: 1.4310x; 1.2909x over previous
#include <cuda_runtime.h>
#include <cuda_bf16.h>

// Fixed shapes per reference setup_inputs
#define BB 8
#define CC 3
#define HH 224
#define WW 224
#define NPIX (HH * WW)          // 50176
#define NSEG 196
#define EE 768
#define NROWS (BB * NSEG)       // 1568
#define ACC_STRIDE 64           // 256 B per row: one LTS hash block per (rep,row)
#define NREP 4                  // accumulator replicas

#define SC_BLOCKS 392           // scatter: (BB*NPIX/4) / 256 exactly
#define NTHREADS 256

// Scratch accumulators: 4 * 1568 * 256 B = 1.6 MB. Zero at module load; the
// project kernel re-zeroes every row it consumes, so each launch leaves the
// array zeroed for the next graph replay.
__device__ float g_acc[(long)NREP * NROWS * ACC_STRIDE];

// ---------------------------------------------------------------------------
__device__ __forceinline__ void red_add_v4(float* addr, float a, float b,
                                           float c, float d) {
    asm volatile("red.global.add.v4.f32 [%0], {%1, %2, %3, %4};"
                 :: "l"(addr), "f"(a), "f"(b), "f"(c), "f"(d) : "memory");
}
__device__ __forceinline__ void red_add_v2(float* addr, float a, float b) {
    asm volatile("red.global.add.v2.f32 [%0], {%1, %2};"
                 :: "l"(addr), "f"(a), "f"(b) : "memory");
}

// ---------------------------------------------------------------------------
// Kernel A: scatter per-(batch,segment) feature sums via vector REDG into
// one of NREP replica accumulators (chosen by blockIdx & 3).  (~2us measured)
// ---------------------------------------------------------------------------
__global__ void __launch_bounds__(NTHREADS, 8)
scatter_kernel(const float* __restrict__ img,
               const int* __restrict__ seg) {
    int t  = blockIdx.x * NTHREADS + threadIdx.x;   // one 4-pixel group
    int b  = t / (NPIX / 4);
    int n4 = t - b * (NPIX / 4);
    int n  = n4 * 4;                                // pixel linear index
    int h  = n / WW;
    int w  = n - h * WW;

    const float4 r4 = *reinterpret_cast<const float4*>(img + ((long)(b * CC + 0) * NPIX + n));
    const float4 g4 = *reinterpret_cast<const float4*>(img + ((long)(b * CC + 1) * NPIX + n));
    const float4 b4 = *reinterpret_cast<const float4*>(img + ((long)(b * CC + 2) * NPIX + n));
    const int4   s4 = *reinterpret_cast<const int4*>(seg + (long)b * NPIX + n);

    const float inv = 1.0f / 223.0f;
    float y = (float)h * inv;

    float rr[4] = {r4.x, r4.y, r4.z, r4.w};
    float gg[4] = {g4.x, g4.y, g4.z, g4.w};
    float bb[4] = {b4.x, b4.y, b4.z, b4.w};
    int   ss[4] = {s4.x, s4.y, s4.z, s4.w};

    float* rep = g_acc + (long)(blockIdx.x & (NREP - 1)) * ((long)NROWS * ACC_STRIDE);

#pragma unroll
    for (int i = 0; i < 4; i++) {
        float x = (float)(w + i) * inv;
        float* base = rep + (long)(b * NSEG + ss[i]) * ACC_STRIDE;
        red_add_v4(base, rr[i], gg[i], bb[i], x);
        red_add_v2(base + 4, y, 1.0f);
    }
}

// ---------------------------------------------------------------------------
// Kernel B: one block per (batch,segment) row.
// 24 threads cooperatively load the 24 acc floats (4 reps x 6) into shared,
// one barrier, then every thread computes 3 output columns from the shared
// broadcast. Finally reset the consumed acc words for the next graph replay.
// ---------------------------------------------------------------------------
__global__ void __launch_bounds__(NTHREADS, 8)
project_kernel(const float* __restrict__ Wm,
               const float* __restrict__ bias,
               float* __restrict__ out) {
    __shared__ float sh[NREP * 6];

    const int s = blockIdx.x;                  // 0..1567
    const int tid = threadIdx.x;

    if (tid < NREP * 6) {
        int rep = tid / 6;
        int j   = tid % 6;
        sh[tid] = g_acc[(long)rep * ((long)NROWS * ACC_STRIDE)
                        + (long)s * ACC_STRIDE + j];
    }
    __syncthreads();

    // Reset the consumed acc words (8 floats x NREP rows) right away; the
    // loads above are complete.  8 float4 stores by one warp.
    if (tid >= 32 && tid < 32 + NREP * 2) {
        int q    = tid - 32;                   // 0..7
        int rep  = q >> 1;
        int half = q & 1;
        reinterpret_cast<float4*>(g_acc + (long)rep * ((long)NROWS * ACC_STRIDE)
                                        + (long)s * ACC_STRIDE)[half] =
            make_float4(0.f, 0.f, 0.f, 0.f);
    }

    float a0 = sh[0] + sh[6] + sh[12] + sh[18];
    float a1 = sh[1] + sh[7] + sh[13] + sh[19];
    float a2 = sh[2] + sh[8] + sh[14] + sh[20];
    float a3 = sh[3] + sh[9] + sh[15] + sh[21];
    float a4 = sh[4] + sh[10] + sh[16] + sh[22];
    float cnt = sh[5] + sh[11] + sh[17] + sh[23];

    bool  empty = !(cnt > 0.0f);
    float invc = empty ? 0.0f : (1.0f / cnt);
    float m0 = a0 * invc;
    float m1 = a1 * invc;
    float m2 = a2 * invc;
    float m3 = a3 * invc;
    float m4 = a4 * invc;

    float* orow = out + (long)s * EE;
#pragma unroll
    for (int k = 0; k < 3; k++) {
        int e = tid + k * NTHREADS;
        float v = m0 * __ldg(Wm + e)
                + m1 * __ldg(Wm + EE + e)
                + m2 * __ldg(Wm + 2 * EE + e)
                + m3 * __ldg(Wm + 3 * EE + e)
                + m4 * __ldg(Wm + 4 * EE + e)
                + __ldg(bias + e);
        orow[e] = empty ? 0.0f : v;
    }
}

// ---------------------------------------------------------------------------
extern "C" void kernel_launch(void* const* d_in, const int* in_sizes, int n_in,
                              void* d_out, int out_size) {
    const float* img  = (const float*)d_in[0];   // [8,3,224,224]
    const int*   seg  = (const int*)d_in[1];     // [8,224,224]
    const float* Wm   = (const float*)d_in[2];   // [5,768]
    const float* bias = (const float*)d_in[3];   // [768]
    float* out = (float*)d_out;                  // [8,196,768]

    (void)in_sizes; (void)n_in; (void)out_size;

    scatter_kernel<<<SC_BLOCKS, NTHREADS>>>(img, seg);
    project_kernel<<<NROWS, NTHREADS>>>(Wm, bias, out);
}

// round 7
// speedup vs baseline: 1.4341x; 1.0022x over previous
#include <cuda_runtime.h>
#include <cuda_bf16.h>

// Fixed shapes per reference setup_inputs
#define BB 8
#define CC 3
#define HH 224
#define WW 224
#define NPIX (HH * WW)          // 50176
#define NSEG 196
#define EE 768
#define NROWS (BB * NSEG)       // 1568
#define ACC_STRIDE 64           // 256 B per row: one LTS hash block per (rep,row)
#define NREP 4                  // accumulator replicas

#define SC_BLOCKS 784           // scatter: (BB*NPIX/2) / 256, 2 px per thread
#define PR_BLOCKS 784           // project: 2 rows per block -> single wave
#define NTHREADS 256

// Scratch accumulators: 4 * 1568 * 256 B = 1.6 MB. Zero at module load; the
// project kernel re-zeroes every row it consumes, so each launch leaves the
// array zeroed for the next graph replay.
__device__ float g_acc[(long)NREP * NROWS * ACC_STRIDE];

// ---------------------------------------------------------------------------
__device__ __forceinline__ void red_add_v4(float* addr, float a, float b,
                                           float c, float d) {
    asm volatile("red.global.add.v4.f32 [%0], {%1, %2, %3, %4};"
                 :: "l"(addr), "f"(a), "f"(b), "f"(c), "f"(d) : "memory");
}
__device__ __forceinline__ void red_add_v2(float* addr, float a, float b) {
    asm volatile("red.global.add.v2.f32 [%0], {%1, %2};"
                 :: "l"(addr), "f"(a), "f"(b) : "memory");
}

// ---------------------------------------------------------------------------
// Kernel A: scatter. 2 pixels per thread, 784 blocks (5.3 blocks/SM for
// deeper latency hiding of the REDG wavefront stream).
// ---------------------------------------------------------------------------
__global__ void __launch_bounds__(NTHREADS, 8)
scatter_kernel(const float* __restrict__ img,
               const int* __restrict__ seg) {
    int t  = blockIdx.x * NTHREADS + threadIdx.x;   // one 2-pixel group
    int b  = t / (NPIX / 2);
    int n2 = t - b * (NPIX / 2);
    int n  = n2 * 2;                                // pixel linear index
    int h  = n / WW;
    int w  = n - h * WW;

    const float2 r2 = *reinterpret_cast<const float2*>(img + ((long)(b * CC + 0) * NPIX + n));
    const float2 g2 = *reinterpret_cast<const float2*>(img + ((long)(b * CC + 1) * NPIX + n));
    const float2 b2 = *reinterpret_cast<const float2*>(img + ((long)(b * CC + 2) * NPIX + n));
    const int2   s2 = *reinterpret_cast<const int2*>(seg + (long)b * NPIX + n);

    const float inv = 1.0f / 223.0f;
    float y = (float)h * inv;

    float rr[2] = {r2.x, r2.y};
    float gg[2] = {g2.x, g2.y};
    float bb[2] = {b2.x, b2.y};
    int   ss[2] = {s2.x, s2.y};

    float* rep = g_acc + (long)(blockIdx.x & (NREP - 1)) * ((long)NROWS * ACC_STRIDE);

#pragma unroll
    for (int i = 0; i < 2; i++) {
        float x = (float)(w + i) * inv;
        float* base = rep + (long)(b * NSEG + ss[i]) * ACC_STRIDE;
        red_add_v4(base, rr[i], gg[i], bb[i], x);
        red_add_v2(base + 4, y, 1.0f);
    }
}

// ---------------------------------------------------------------------------
// Kernel B: project. 2 rows per block (warps 0-3 -> row0, warps 4-7 -> row1),
// 784 blocks = single wave. Each warp redundantly loads its row's 24 acc
// floats (lanes 0-23, plain cached loads) and reduces them with shfl — no
// barrier on the critical path, so W __ldg loads overlap the acc loads.
// __syncthreads only orders the scratch reset at the end.
// ---------------------------------------------------------------------------
__global__ void __launch_bounds__(NTHREADS, 8)
project_kernel(const float* __restrict__ Wm,
               const float* __restrict__ bias,
               float* __restrict__ out) {
    const int tid  = threadIdx.x;
    const int half = tid >> 7;                 // 0 or 1
    const int t128 = tid & 127;                // thread-in-half
    const int lane = tid & 31;
    const int s    = blockIdx.x * 2 + half;    // row 0..1567

    // lanes 0-23 of every warp load this row's acc values: rep = lane/6, j = lane%6
    float v = 0.0f;
    if (lane < NREP * 6) {
        int rep = lane / 6;
        int j   = lane - rep * 6;
        v = g_acc[(long)rep * ((long)NROWS * ACC_STRIDE)
                  + (long)s * ACC_STRIDE + j];
    }

    float a0 = __shfl_sync(0xffffffffu, v, 0)  + __shfl_sync(0xffffffffu, v, 6)
             + __shfl_sync(0xffffffffu, v, 12) + __shfl_sync(0xffffffffu, v, 18);
    float a1 = __shfl_sync(0xffffffffu, v, 1)  + __shfl_sync(0xffffffffu, v, 7)
             + __shfl_sync(0xffffffffu, v, 13) + __shfl_sync(0xffffffffu, v, 19);
    float a2 = __shfl_sync(0xffffffffu, v, 2)  + __shfl_sync(0xffffffffu, v, 8)
             + __shfl_sync(0xffffffffu, v, 14) + __shfl_sync(0xffffffffu, v, 20);
    float a3 = __shfl_sync(0xffffffffu, v, 3)  + __shfl_sync(0xffffffffu, v, 9)
             + __shfl_sync(0xffffffffu, v, 15) + __shfl_sync(0xffffffffu, v, 21);
    float a4 = __shfl_sync(0xffffffffu, v, 4)  + __shfl_sync(0xffffffffu, v, 10)
             + __shfl_sync(0xffffffffu, v, 16) + __shfl_sync(0xffffffffu, v, 22);
    float cnt = __shfl_sync(0xffffffffu, v, 5)  + __shfl_sync(0xffffffffu, v, 11)
              + __shfl_sync(0xffffffffu, v, 17) + __shfl_sync(0xffffffffu, v, 23);

    bool  empty = !(cnt > 0.0f);
    float invc = empty ? 0.0f : (1.0f / cnt);
    float m0 = a0 * invc;
    float m1 = a1 * invc;
    float m2 = a2 * invc;
    float m3 = a3 * invc;
    float m4 = a4 * invc;

    float* orow = out + (long)s * EE;
#pragma unroll
    for (int k = 0; k < 6; k++) {              // 768 / 128 = 6 cols per thread
        int e = t128 + k * 128;
        float w = m0 * __ldg(Wm + e)
                + m1 * __ldg(Wm + EE + e)
                + m2 * __ldg(Wm + 2 * EE + e)
                + m3 * __ldg(Wm + 3 * EE + e)
                + m4 * __ldg(Wm + 4 * EE + e)
                + __ldg(bias + e);
        orow[e] = empty ? 0.0f : w;
    }

    // Reset the consumed acc words for the next replay. Must come after ALL
    // warps (both halves) finished reading -> one barrier, off critical path.
    __syncthreads();
    if (tid < 16) {                            // 2 rows * NREP * 2 float4
        int q    = tid;                        // row = q/8, rep = (q/2)%4, half4 = q&1
        int rrow = blockIdx.x * 2 + (q >> 3);
        int rep  = (q >> 1) & 3;
        int h4   = q & 1;
        reinterpret_cast<float4*>(g_acc + (long)rep * ((long)NROWS * ACC_STRIDE)
                                        + (long)rrow * ACC_STRIDE)[h4] =
            make_float4(0.f, 0.f, 0.f, 0.f);
    }
}

// ---------------------------------------------------------------------------
extern "C" void kernel_launch(void* const* d_in, const int* in_sizes, int n_in,
                              void* d_out, int out_size) {
    const float* img  = (const float*)d_in[0];   // [8,3,224,224]
    const int*   seg  = (const int*)d_in[1];     // [8,224,224]
    const float* Wm   = (const float*)d_in[2];   // [5,768]
    const float* bias = (const float*)d_in[3];   // [768]
    float* out = (float*)d_out;                  // [8,196,768]

    (void)in_sizes; (void)n_in; (void)out_size;

    scatter_kernel<<<SC_BLOCKS, NTHREADS>>>(img, seg);
    project_kernel<<<PR_BLOCKS, NTHREADS>>>(Wm, bias, out);
}